// round 2
// baseline (speedup 1.0000x reference)
#include <cuda_runtime.h>
#include <cuda_bf16.h>
#include <math.h>

// ---------------- problem constants ----------------
#define NN   100000
#define EE   1600000
#define TT   (NN + EE)      // edges incl. self loops
#define INC  128
#define HID  32
#define HEADS 4
#define OUTC 16
#define GG   128
#define NEG  0.2f

// ---------------- scratch (static device globals; no allocs) ----------------
__device__ __align__(16) int    g_src[TT];
__device__ __align__(16) int    g_dst[TT];
__device__ __align__(16) float  g_h1 [NN * 128];
__device__ __align__(16) float  g_as1[NN * 4];
__device__ __align__(16) float  g_ad1[NN * 4];
__device__ __align__(16) float  g_den1[NN * 4];
__device__ __align__(16) float  g_out1[NN * 128];
__device__ __align__(16) float  g_h2 [NN * 32];
__device__ __align__(16) float  g_as2[NN];
__device__ __align__(16) float  g_ad2[NN];
__device__ __align__(16) float  g_den2[NN];
__device__ __align__(16) float  g_out2[NN * 32];
__device__ __align__(16) float  g_pool[GG * 32];
__device__ __align__(16) float  g_cnt [GG];

// ---------------- helpers ----------------
__device__ __forceinline__ float lrelu(float x) { return x > 0.f ? x : NEG * x; }
__device__ __forceinline__ float elu1(float x)  { return x > 0.f ? x : expm1f(x); }

__device__ __forceinline__ void red_add_v4(float* addr, float a, float b, float c, float d) {
    asm volatile("red.global.add.v4.f32 [%0], {%1,%2,%3,%4};"
                 :: "l"(addr), "f"(a), "f"(b), "f"(c), "f"(d) : "memory");
}

// ---------------- kernels ----------------

// zero all accumulators (out1 is the biggest: N*128)
__global__ void k_zero(int N) {
    int i = blockIdx.x * blockDim.x + threadIdx.x;
    if (i < N * 128) g_out1[i] = 0.f;
    if (i < N * 32)  g_out2[i] = 0.f;
    if (i < N * 4)   g_den1[i] = 0.f;
    if (i < N)       g_den2[i] = 0.f;
    if (i < GG * 32) g_pool[i] = 0.f;
    if (i < GG)      g_cnt[i]  = 0.f;
}

// build int32 edge lists with self loops appended (indices clamped defensively)
__global__ void k_build_edges(const int* __restrict__ ei, int E, int TE, int N) {
    int i = blockIdx.x * blockDim.x + threadIdx.x;
    if (i >= TE) return;
    int s, d;
    if (i < E) {
        s = ei[i];
        d = ei[E + i];
    } else {
        s = i - E;
        d = i - E;
    }
    s = min(max(s, 0), N - 1);
    d = min(max(d, 0), N - 1);
    g_src[i] = s;
    g_dst[i] = d;
}

// GEMM1: h1 = (x*nw) @ W1  [N,128]x[128,128], fused attention coefficients.
// 64x128 tile per block, 256 threads, 8x4 micro-tile per thread.
__global__ void __launch_bounds__(256) k_gemm1(
    const float* __restrict__ x, const float* __restrict__ nw,
    const float* __restrict__ W1,
    const float* __restrict__ attS, const float* __restrict__ attD, int N)
{
    __shared__ float As[64 * 32];    // [m][k]
    __shared__ float Ws[32 * 128];   // [k][n]
    const int tid = threadIdx.x;
    const int r0  = blockIdx.x * 64;
    const int tx  = tid & 31;        // col group (x4)
    const int ty  = tid >> 5;        // row group (x8)

    float acc[8][4];
    #pragma unroll
    for (int i = 0; i < 8; i++)
        #pragma unroll
        for (int j = 0; j < 4; j++) acc[i][j] = 0.f;

    for (int kk = 0; kk < 128; kk += 32) {
        #pragma unroll
        for (int i = 0; i < 8; i++) {
            int e = tid + i * 256;
            int m = e >> 5, k = e & 31;
            int row = r0 + m;
            float v = 0.f;
            if (row < N) v = x[row * 128 + kk + k] * nw[row];
            As[m * 32 + k] = v;
        }
        #pragma unroll
        for (int i = 0; i < 16; i++) {
            int e = tid + i * 256;
            int k = e >> 7, n = e & 127;
            Ws[k * 128 + n] = W1[(kk + k) * 128 + n];
        }
        __syncthreads();
        #pragma unroll
        for (int k = 0; k < 32; k++) {
            const float4 b = *(const float4*)&Ws[k * 128 + tx * 4];
            float a[8];
            #pragma unroll
            for (int i = 0; i < 8; i++) a[i] = As[(ty * 8 + i) * 32 + k];
            #pragma unroll
            for (int i = 0; i < 8; i++) {
                acc[i][0] += a[i] * b.x; acc[i][1] += a[i] * b.y;
                acc[i][2] += a[i] * b.z; acc[i][3] += a[i] * b.w;
            }
        }
        __syncthreads();
    }

    // epilogue: store h1, reduce a_src/a_dst per head (head = tx>>3, 8-lane groups)
    const float4 asv = *(const float4*)&attS[tx * 4];
    const float4 adv = *(const float4*)&attD[tx * 4];
    const int head = tx >> 3;
    #pragma unroll
    for (int i = 0; i < 8; i++) {
        int row = r0 + ty * 8 + i;
        float4 o; o.x = acc[i][0]; o.y = acc[i][1]; o.z = acc[i][2]; o.w = acc[i][3];
        if (row < N) *(float4*)&g_h1[row * 128 + tx * 4] = o;
        float ps = o.x * asv.x + o.y * asv.y + o.z * asv.z + o.w * asv.w;
        float pd = o.x * adv.x + o.y * adv.y + o.z * adv.z + o.w * adv.w;
        #pragma unroll
        for (int ofs = 1; ofs < 8; ofs <<= 1) {
            ps += __shfl_xor_sync(0xffffffffu, ps, ofs);
            pd += __shfl_xor_sync(0xffffffffu, pd, ofs);
        }
        if ((tx & 7) == 0 && row < N) {
            g_as1[row * 4 + head] = ps;
            g_ad1[row * 4 + head] = pd;
        }
    }
}

// layer-1 softmax denominators: one thread per edge, 4 heads via v4 reduction
__global__ void k_edge_denom1(int TE) {
    int i = blockIdx.x * blockDim.x + threadIdx.x;
    if (i >= TE) return;
    int s = g_src[i], d = g_dst[i];
    float4 as = *(const float4*)&g_as1[s * 4];
    float4 ad = *(const float4*)&g_ad1[d * 4];
    float w0 = expf(lrelu(as.x + ad.x));
    float w1 = expf(lrelu(as.y + ad.y));
    float w2 = expf(lrelu(as.z + ad.z));
    float w3 = expf(lrelu(as.w + ad.w));
    red_add_v4(&g_den1[d * 4], w0, w1, w2, w3);
}

// layer-1 aggregation: one warp per edge; lane handles 4 contiguous channels
__global__ void __launch_bounds__(256) k_edge_agg1(int TE) {
    int w = (blockIdx.x * blockDim.x + threadIdx.x) >> 5;
    if (w >= TE) return;
    int lane = threadIdx.x & 31;
    int s = g_src[w], d = g_dst[w];
    int head = lane >> 3;                       // lane*4 channels -> head lane/8
    float asv = g_as1[s * 4 + head];
    float adv = g_ad1[d * 4 + head];
    float den = g_den1[d * 4 + head];
    float alpha = expf(lrelu(asv + adv)) / den;
    float4 hv = *(const float4*)&g_h1[s * 128 + lane * 4];
    red_add_v4(&g_out1[d * 128 + lane * 4],
               hv.x * alpha, hv.y * alpha, hv.z * alpha, hv.w * alpha);
}

// GEMM2: h2 = elu(out1 + b1) @ W2 [128->32], fused ELU load + attention coeffs.
// One warp per row, W2 staged in smem, x row broadcast via shfl.
__global__ void __launch_bounds__(128) k_gemm2(
    const float* __restrict__ b1, const float* __restrict__ W2,
    const float* __restrict__ attS2, const float* __restrict__ attD2, int N)
{
    __shared__ float Ws[128 * 32];
    int tid = threadIdx.x;
    for (int i = tid; i < 128 * 32; i += 128) Ws[i] = W2[i];
    __syncthreads();
    int lane = tid & 31, wp = tid >> 5;
    float4 b1v = *(const float4*)&b1[lane * 4];
    float attS = attS2[lane], attD = attD2[lane];

    for (int row = blockIdx.x * 4 + wp; row < N; row += gridDim.x * 4) {
        float4 xv = *(const float4*)&g_out1[row * 128 + lane * 4];
        float xq[4];
        xq[0] = elu1(xv.x + b1v.x);
        xq[1] = elu1(xv.y + b1v.y);
        xq[2] = elu1(xv.z + b1v.z);
        xq[3] = elu1(xv.w + b1v.w);
        float acc = 0.f;
        #pragma unroll
        for (int k = 0; k < 128; k++) {
            float xk = __shfl_sync(0xffffffffu, xq[k & 3], k >> 2);
            acc += xk * Ws[k * 32 + lane];
        }
        g_h2[row * 32 + lane] = acc;
        float ps = acc * attS, pd = acc * attD;
        #pragma unroll
        for (int o = 16; o; o >>= 1) {
            ps += __shfl_xor_sync(0xffffffffu, ps, o);
            pd += __shfl_xor_sync(0xffffffffu, pd, o);
        }
        if (lane == 0) { g_as2[row] = ps; g_ad2[row] = pd; }
    }
}

__global__ void k_edge_denom2(int TE) {
    int i = blockIdx.x * blockDim.x + threadIdx.x;
    if (i >= TE) return;
    int s = g_src[i], d = g_dst[i];
    float wv = expf(lrelu(g_as2[s] + g_ad2[d]));
    atomicAdd(&g_den2[d], wv);
}

// layer-2 aggregation: 8 lanes per edge (32 channels = 8 x float4)
__global__ void __launch_bounds__(256) k_edge_agg2(int TE) {
    int gid = blockIdx.x * blockDim.x + threadIdx.x;
    int e = gid >> 3;
    if (e >= TE) return;
    int sub = gid & 7;
    int s = g_src[e], d = g_dst[e];
    float alpha = expf(lrelu(g_as2[s] + g_ad2[d])) / g_den2[d];
    float4 hv = *(const float4*)&g_h2[s * 32 + sub * 4];
    red_add_v4(&g_out2[d * 32 + sub * 4],
               hv.x * alpha, hv.y * alpha, hv.z * alpha, hv.w * alpha);
}

// ELU(out2+b2) -> pool sums + counts
__global__ void k_pool(const int* __restrict__ batch,
                       const float* __restrict__ b2, int N)
{
    int gid = blockIdx.x * blockDim.x + threadIdx.x;
    int n = gid >> 5;
    if (n >= N) return;
    int c = gid & 31;
    float v = elu1(g_out2[n * 32 + c] + b2[c]);
    int g = batch[n];
    g = min(max(g, 0), GG - 1);
    atomicAdd(&g_pool[g * 32 + c], v);
    if (c == 0) atomicAdd(&g_cnt[g], 1.0f);
}

// final FC: out[g,o] = (pool[g]/cnt[g]) @ fcW + fcb
__global__ void k_final(const float* __restrict__ fcW,
                        const float* __restrict__ fcb, float* __restrict__ out)
{
    int idx = blockIdx.x * blockDim.x + threadIdx.x;
    if (idx >= GG * OUTC) return;
    int g = idx >> 4, o = idx & 15;
    float c = fmaxf(g_cnt[g], 1.0f);
    float s = 0.f;
    #pragma unroll
    for (int k = 0; k < 32; k++)
        s += (g_pool[g * 32 + k] / c) * fcW[k * OUTC + o];
    out[idx] = s + fcb[o];
}

// ---------------- launch ----------------
extern "C" void kernel_launch(void* const* d_in, const int* in_sizes, int n_in,
                              void* d_out, int out_size)
{
    const float* x     = (const float*)d_in[0];
    const int*   ei    = (const int*)d_in[1];     // int64 in reference -> int32 in harness
    const int*   batch = (const int*)d_in[2];
    const float* nw    = (const float*)d_in[3];
    const float* W1    = (const float*)d_in[4];
    const float* as1   = (const float*)d_in[5];
    const float* ad1   = (const float*)d_in[6];
    const float* b1    = (const float*)d_in[7];
    const float* W2    = (const float*)d_in[8];
    const float* as2   = (const float*)d_in[9];
    const float* ad2   = (const float*)d_in[10];
    const float* b2    = (const float*)d_in[11];
    const float* fcW   = (const float*)d_in[12];
    const float* fcb   = (const float*)d_in[13];
    float* out = (float*)d_out;

    const int N  = in_sizes[0] / INC;
    const int E  = in_sizes[1] / 2;
    const int TE = E + N;

    k_zero<<<(N * 128 + 255) / 256, 256>>>(N);
    k_build_edges<<<(TE + 255) / 256, 256>>>(ei, E, TE, N);
    k_gemm1<<<(N + 63) / 64, 256>>>(x, nw, W1, as1, ad1, N);
    k_edge_denom1<<<(TE + 255) / 256, 256>>>(TE);
    {
        long long thr = (long long)TE * 32;
        k_edge_agg1<<<(unsigned)((thr + 255) / 256), 256>>>(TE);
    }
    k_gemm2<<<2048, 128>>>(b1, W2, as2, ad2, N);
    k_edge_denom2<<<(TE + 255) / 256, 256>>>(TE);
    {
        long long thr = (long long)TE * 8;
        k_edge_agg2<<<(unsigned)((thr + 255) / 256), 256>>>(TE);
    }
    k_pool<<<(N * 32 + 255) / 256, 256>>>(batch, b2, N);
    k_final<<<(GG * OUTC + 255) / 256, 256>>>(fcW, fcb, out);
}

// round 3
// speedup vs baseline: 1.6739x; 1.6739x over previous
#include <cuda_runtime.h>
#include <cuda_bf16.h>
#include <math.h>

// ---------------- problem constants ----------------
#define NN   100000
#define EE   1600000
#define TT   (NN + EE)      // edges incl. self loops
#define INC  128
#define HID  32
#define HEADS 4
#define OUTC 16
#define GG   128
#define NEG  0.2f

// ---------------- scratch (static device globals; no allocs) ----------------
__device__ __align__(16) int    g_srcE[TT];     // raw edge src
__device__ __align__(16) int    g_dstE[TT];     // raw edge dst
__device__ __align__(16) int    g_srcs[TT];     // CSR: src sorted by dst
__device__ __align__(16) int    g_deg [NN + 1];
__device__ __align__(16) int    g_scan[NN];
__device__ __align__(16) int    g_off [NN + 1];
__device__ __align__(16) int    g_cur [NN];
__device__ __align__(16) int    g_bsum[256];
__device__ __align__(16) int    g_boff[256];
__device__ __align__(16) float  g_h1 [NN * 128];
__device__ __align__(16) float  g_as1[NN * 4];
__device__ __align__(16) float  g_ad1[NN * 4];
__device__ __align__(16) float  g_h2 [NN * 32];
__device__ __align__(16) float  g_as2[NN];
__device__ __align__(16) float  g_ad2[NN];
__device__ __align__(16) float  g_pool[GG * 32];
__device__ __align__(16) float  g_cnt [GG];

// ---------------- helpers ----------------
__device__ __forceinline__ float lrelu(float x) { return x > 0.f ? x : NEG * x; }
__device__ __forceinline__ float elu1(float x)  { return x > 0.f ? x : expm1f(x); }

// ---------------- kernels ----------------

// zero counters
__global__ void k_zero(int N) {
    int i = blockIdx.x * blockDim.x + threadIdx.x;
    if (i <= N)      g_deg[i] = 0;
    if (i < GG * 32) g_pool[i] = 0.f;
    if (i < GG)      g_cnt[i]  = 0.f;
}

// build int32 edge lists with self loops appended + dst histogram
__global__ void k_build_edges(const int* __restrict__ ei, int E, int TE, int N) {
    int i = blockIdx.x * blockDim.x + threadIdx.x;
    if (i >= TE) return;
    int s, d;
    if (i < E) { s = ei[i]; d = ei[E + i]; }
    else       { s = i - E; d = i - E; }
    s = min(max(s, 0), N - 1);
    d = min(max(d, 0), N - 1);
    g_srcE[i] = s;
    g_dstE[i] = d;
    atomicAdd(&g_deg[d], 1);
}

// --- 3-phase exclusive scan of g_deg[0..N) -> g_off ---
__global__ void k_scan1(int N) {
    __shared__ int sh[1024];
    int i = blockIdx.x * 1024 + threadIdx.x;
    int v = (i < N) ? g_deg[i] : 0;
    sh[threadIdx.x] = v;
    __syncthreads();
    #pragma unroll
    for (int o = 1; o < 1024; o <<= 1) {
        int t = (threadIdx.x >= o) ? sh[threadIdx.x - o] : 0;
        __syncthreads();
        sh[threadIdx.x] += t;
        __syncthreads();
    }
    if (i < N) g_scan[i] = sh[threadIdx.x];
    if (threadIdx.x == 1023) g_bsum[blockIdx.x] = sh[1023];
}

__global__ void k_scan2(int NB) {
    __shared__ int sh[256];
    int t = threadIdx.x;
    int v = (t < NB) ? g_bsum[t] : 0;
    sh[t] = v;
    __syncthreads();
    #pragma unroll
    for (int o = 1; o < 256; o <<= 1) {
        int a = (t >= o) ? sh[t - o] : 0;
        __syncthreads();
        sh[t] += a;
        __syncthreads();
    }
    g_boff[t] = sh[t] - v;   // exclusive
}

__global__ void k_scan3(int N, int TE) {
    int i = blockIdx.x * 1024 + threadIdx.x;
    if (i < N) {
        int off = g_scan[i] - g_deg[i] + g_boff[i >> 10];
        g_off[i] = off;
        g_cur[i] = off;
    }
    if (i == 0) g_off[N] = TE;
}

// scatter edges into CSR order
__global__ void k_scatter(int TE) {
    int i = blockIdx.x * blockDim.x + threadIdx.x;
    if (i >= TE) return;
    int d = g_dstE[i];
    int p = atomicAdd(&g_cur[d], 1);
    g_srcs[p] = g_srcE[i];
}

// GEMM1: h1 = (x*nw) @ W1  [N,128]x[128,128], fused attention coefficients.
__global__ void __launch_bounds__(256) k_gemm1(
    const float* __restrict__ x, const float* __restrict__ nw,
    const float* __restrict__ W1,
    const float* __restrict__ attS, const float* __restrict__ attD, int N)
{
    __shared__ float As[64 * 32];    // [m][k]
    __shared__ float Ws[32 * 128];   // [k][n]
    const int tid = threadIdx.x;
    const int r0  = blockIdx.x * 64;
    const int tx  = tid & 31;
    const int ty  = tid >> 5;

    float acc[8][4];
    #pragma unroll
    for (int i = 0; i < 8; i++)
        #pragma unroll
        for (int j = 0; j < 4; j++) acc[i][j] = 0.f;

    for (int kk = 0; kk < 128; kk += 32) {
        #pragma unroll
        for (int i = 0; i < 8; i++) {
            int e = tid + i * 256;
            int m = e >> 5, k = e & 31;
            int row = r0 + m;
            float v = 0.f;
            if (row < N) v = x[row * 128 + kk + k] * nw[row];
            As[m * 32 + k] = v;
        }
        #pragma unroll
        for (int i = 0; i < 16; i++) {
            int e = tid + i * 256;
            int k = e >> 7, n = e & 127;
            Ws[k * 128 + n] = W1[(kk + k) * 128 + n];
        }
        __syncthreads();
        #pragma unroll
        for (int k = 0; k < 32; k++) {
            const float4 b = *(const float4*)&Ws[k * 128 + tx * 4];
            float a[8];
            #pragma unroll
            for (int i = 0; i < 8; i++) a[i] = As[(ty * 8 + i) * 32 + k];
            #pragma unroll
            for (int i = 0; i < 8; i++) {
                acc[i][0] += a[i] * b.x; acc[i][1] += a[i] * b.y;
                acc[i][2] += a[i] * b.z; acc[i][3] += a[i] * b.w;
            }
        }
        __syncthreads();
    }

    const float4 asv = *(const float4*)&attS[tx * 4];
    const float4 adv = *(const float4*)&attD[tx * 4];
    const int head = tx >> 3;
    #pragma unroll
    for (int i = 0; i < 8; i++) {
        int row = r0 + ty * 8 + i;
        float4 o; o.x = acc[i][0]; o.y = acc[i][1]; o.z = acc[i][2]; o.w = acc[i][3];
        if (row < N) *(float4*)&g_h1[row * 128 + tx * 4] = o;
        float ps = o.x * asv.x + o.y * asv.y + o.z * asv.z + o.w * asv.w;
        float pd = o.x * adv.x + o.y * adv.y + o.z * adv.z + o.w * adv.w;
        #pragma unroll
        for (int ofs = 1; ofs < 8; ofs <<= 1) {
            ps += __shfl_xor_sync(0xffffffffu, ps, ofs);
            pd += __shfl_xor_sync(0xffffffffu, pd, ofs);
        }
        if ((tx & 7) == 0 && row < N) {
            g_as1[row * 4 + head] = ps;
            g_ad1[row * 4 + head] = pd;
        }
    }
}

// Fused layer-1 aggregation (CSR gather, softmax in registers) + ELU + GEMM2
// + layer-2 attention coefficients. One warp per destination node.
__global__ void __launch_bounds__(256) k_agg1_gemm2(
    const float* __restrict__ b1, const float* __restrict__ W2,
    const float* __restrict__ attS2, const float* __restrict__ attD2, int N)
{
    __shared__ float Ws[128 * 32];
    __shared__ float Qs[8][128];
    const int tid = threadIdx.x;
    for (int i = tid; i < 128 * 32; i += 256) Ws[i] = W2[i];
    __syncthreads();

    const int warp = tid >> 5, lane = tid & 31;
    const int node = blockIdx.x * 8 + warp;
    if (node >= N) return;
    const int head = lane >> 3;

    const float ad = g_ad1[node * 4 + head];
    const int e0 = g_off[node], e1 = g_off[node + 1];

    float4 acc = make_float4(0.f, 0.f, 0.f, 0.f);
    float den = 0.f;
    int e = e0;
    for (; e + 2 <= e1; e += 2) {
        int s0 = g_srcs[e], s1 = g_srcs[e + 1];
        float w0 = __expf(lrelu(g_as1[s0 * 4 + head] + ad));
        float w1 = __expf(lrelu(g_as1[s1 * 4 + head] + ad));
        float4 h0 = *(const float4*)&g_h1[s0 * 128 + lane * 4];
        float4 h1v = *(const float4*)&g_h1[s1 * 128 + lane * 4];
        den += w0 + w1;
        acc.x += w0 * h0.x + w1 * h1v.x;
        acc.y += w0 * h0.y + w1 * h1v.y;
        acc.z += w0 * h0.z + w1 * h1v.z;
        acc.w += w0 * h0.w + w1 * h1v.w;
    }
    if (e < e1) {
        int s0 = g_srcs[e];
        float w0 = __expf(lrelu(g_as1[s0 * 4 + head] + ad));
        float4 h0 = *(const float4*)&g_h1[s0 * 128 + lane * 4];
        den += w0;
        acc.x += w0 * h0.x; acc.y += w0 * h0.y;
        acc.z += w0 * h0.z; acc.w += w0 * h0.w;
    }
    const float inv = 1.f / den;
    const float4 b1v = *(const float4*)&b1[lane * 4];
    Qs[warp][lane * 4 + 0] = elu1(acc.x * inv + b1v.x);
    Qs[warp][lane * 4 + 1] = elu1(acc.y * inv + b1v.y);
    Qs[warp][lane * 4 + 2] = elu1(acc.z * inv + b1v.z);
    Qs[warp][lane * 4 + 3] = elu1(acc.w * inv + b1v.w);
    __syncwarp();

    // GEMM2 row: h2[node, lane] = q . W2[:, lane]
    float h2v = 0.f;
    #pragma unroll
    for (int k = 0; k < 128; k++)
        h2v += Qs[warp][k] * Ws[k * 32 + lane];
    g_h2[node * 32 + lane] = h2v;

    float ps = h2v * attS2[lane], pd = h2v * attD2[lane];
    #pragma unroll
    for (int o = 16; o; o >>= 1) {
        ps += __shfl_xor_sync(0xffffffffu, ps, o);
        pd += __shfl_xor_sync(0xffffffffu, pd, o);
    }
    if (lane == 0) { g_as2[node] = ps; g_ad2[node] = pd; }
}

// Fused layer-2 aggregation + ELU + global mean-pool accumulation.
// One warp per destination node; lane = channel.
__global__ void __launch_bounds__(256) k_agg2_pool(
    const int* __restrict__ batch, const float* __restrict__ b2, int N)
{
    const int tid = threadIdx.x;
    const int warp = tid >> 5, lane = tid & 31;
    const int node = blockIdx.x * 8 + warp;
    if (node >= N) return;

    const float ad = g_ad2[node];
    const int e0 = g_off[node], e1 = g_off[node + 1];
    float acc = 0.f, den = 0.f;
    int e = e0;
    for (; e + 2 <= e1; e += 2) {
        int s0 = g_srcs[e], s1 = g_srcs[e + 1];
        float w0 = __expf(lrelu(g_as2[s0] + ad));
        float w1 = __expf(lrelu(g_as2[s1] + ad));
        float v0 = g_h2[s0 * 32 + lane];
        float v1 = g_h2[s1 * 32 + lane];
        den += w0 + w1;
        acc += w0 * v0 + w1 * v1;
    }
    if (e < e1) {
        int s0 = g_srcs[e];
        float w0 = __expf(lrelu(g_as2[s0] + ad));
        acc += w0 * g_h2[s0 * 32 + lane];
        den += w0;
    }
    float v = elu1(acc / den + b2[lane]);
    int g = batch[node];
    g = min(max(g, 0), GG - 1);
    atomicAdd(&g_pool[g * 32 + lane], v);
    if (lane == 0) atomicAdd(&g_cnt[g], 1.0f);
}

// final FC: out[g,o] = (pool[g]/cnt[g]) @ fcW + fcb
__global__ void k_final(const float* __restrict__ fcW,
                        const float* __restrict__ fcb, float* __restrict__ out)
{
    int idx = blockIdx.x * blockDim.x + threadIdx.x;
    if (idx >= GG * OUTC) return;
    int g = idx >> 4, o = idx & 15;
    float c = fmaxf(g_cnt[g], 1.0f);
    float s = 0.f;
    #pragma unroll
    for (int k = 0; k < 32; k++)
        s += (g_pool[g * 32 + k] / c) * fcW[k * OUTC + o];
    out[idx] = s + fcb[o];
}

// ---------------- launch ----------------
extern "C" void kernel_launch(void* const* d_in, const int* in_sizes, int n_in,
                              void* d_out, int out_size)
{
    const float* x     = (const float*)d_in[0];
    const int*   ei    = (const int*)d_in[1];
    const int*   batch = (const int*)d_in[2];
    const float* nw    = (const float*)d_in[3];
    const float* W1    = (const float*)d_in[4];
    const float* as1   = (const float*)d_in[5];
    const float* ad1   = (const float*)d_in[6];
    const float* b1    = (const float*)d_in[7];
    const float* W2    = (const float*)d_in[8];
    const float* as2   = (const float*)d_in[9];
    const float* ad2   = (const float*)d_in[10];
    const float* b2    = (const float*)d_in[11];
    const float* fcW   = (const float*)d_in[12];
    const float* fcb   = (const float*)d_in[13];
    float* out = (float*)d_out;

    const int N  = in_sizes[0] / INC;
    const int E  = in_sizes[1] / 2;
    const int TE = E + N;
    const int NB = (N + 1023) / 1024;

    k_zero<<<(N + 256) / 256, 256>>>(N);
    k_build_edges<<<(TE + 255) / 256, 256>>>(ei, E, TE, N);
    k_scan1<<<NB, 1024>>>(N);
    k_scan2<<<1, 256>>>(NB);
    k_scan3<<<NB, 1024>>>(N, TE);
    k_scatter<<<(TE + 255) / 256, 256>>>(TE);
    k_gemm1<<<(N + 63) / 64, 256>>>(x, nw, W1, as1, ad1, N);
    k_agg1_gemm2<<<(N + 7) / 8, 256>>>(b1, W2, as2, ad2, N);
    k_agg2_pool<<<(N + 7) / 8, 256>>>(batch, b2, N);
    k_final<<<(GG * OUTC + 255) / 256, 256>>>(fcW, fcb, out);
}